// round 4
// baseline (speedup 1.0000x reference)
#include <cuda_runtime.h>
#include <cstdint>

// Problem constants
#define BN   4
#define CN   128
#define HN   128
#define WN   128
#define COUT 128
#define DGN  8
#define CG   16
#define KK   9
#define HO   128
#define WO   128
#define NS   72        // dg*9+k positions

typedef unsigned long long u64;

// Scratch: x transposed to (B, DG, H, W, Cg) and weight to (DG*K, Cg, Cout)
__device__ __align__(16) float g_xt[BN * DGN * HN * WN * CG];   // 33.5 MB
__device__ __align__(16) float g_wt[NS * CG * COUT];            // 576 KB

__device__ __forceinline__ u64 pack2(float a, float b) {
    u64 r;
    asm("mov.b64 %0, {%1, %2};" : "=l"(r) : "f"(a), "f"(b));
    return r;
}
__device__ __forceinline__ void ffma2(u64& d, u64 a, u64 b) {
    asm("fma.rn.f32x2 %0, %1, %2, %0;" : "+l"(d) : "l"(a), "l"(b));
}

// ---------------------------------------------------------------------------
// Kernel 1: transpose x (B,C,H,W) -> (B, DG, H, W, Cg)
// ---------------------------------------------------------------------------
__global__ void transpose_x_kernel(const float* __restrict__ x) {
    int blk = blockIdx.x;          // (b*DGN + dg)*HN + y
    int y   = blk & (HN - 1);
    int bdg = blk >> 7;
    int b   = bdg >> 3;
    int dg  = bdg & 7;
    int t   = threadIdx.x;

    __shared__ float sm[CG][WN + 1];
    #pragma unroll
    for (int c = 0; c < CG; c++)
        sm[c][t] = x[((b * CN + dg * CG + c) * HN + y) * WN + t];
    __syncthreads();

    float* outp = g_xt + ((bdg * HN + y) * WN + t) * CG;
    #pragma unroll
    for (int i = 0; i < 4; i++) {
        float4 v = make_float4(sm[i * 4 + 0][t], sm[i * 4 + 1][t],
                               sm[i * 4 + 2][t], sm[i * 4 + 3][t]);
        *(float4*)(outp + i * 4) = v;
    }
}

// ---------------------------------------------------------------------------
// Kernel 2: transpose weight (Cout, C, K) -> (DG*K, Cg, Cout)
// ---------------------------------------------------------------------------
__global__ void transpose_w_kernel(const float* __restrict__ w) {
    int j = blockIdx.x * 256 + threadIdx.x;
    if (j >= NS * CG * COUT) return;
    int co = j & (COUT - 1);
    int c  = (j >> 7) & (CG - 1);
    int dk = j >> 11;              // dg*KK + k
    int k  = dk % KK;
    int dg = dk / KK;
    g_wt[j] = w[(co * CN + dg * CG + c) * KK + k];
}

// ---------------------------------------------------------------------------
// Kernel 3: fused deformable sampling + implicit GEMM, pure-f32x2 inner loop.
// One block per (b, ho): 128 pixels x 128 Cout, 256 threads.
// GEMM mapping (conflict-minimized): warp wid, lane l:
//   px_grp = (l&7)|((wid&1)<<3), co_grp = (l>>3)|((wid>>1)<<2)
// Weight tile staged PRE-DUPLICATED as float2{w,w} so the inner loop has
// zero mov.b64 packs: 8 LDS.128 + 32 FFMA2 per channel.
// ---------------------------------------------------------------------------
__global__ __launch_bounds__(256, 2)
void dcn_main_kernel(const float* __restrict__ offset,
                     const float* __restrict__ mask,
                     const float* __restrict__ bias,
                     float*       __restrict__ out) {
    int blk = blockIdx.x;          // b*HO + ho
    int ho  = blk & (HO - 1);
    int b   = blk >> 7;
    int t   = threadIdx.x;
    int wid = t >> 5;
    int lane = t & 31;

    __shared__ __align__(16) float  s_tile[CG][WO];    // sampled [c][pixel]  8KB
    __shared__ __align__(16) float2 w_dup[CG][COUT];   // dup weights [c][co] 16KB

    int px_grp = (lane & 7) | ((wid & 1) << 3);
    int co_grp = (lane >> 3) | ((wid >> 1) << 2);
    int p_base  = px_grp * 8;
    int co_base = co_grp * 8;

    // sampling role
    int wo = t & (WO - 1);
    int ch = (t >> 7) * 8;         // 0 or 8

    u64 acc2[8][4];
    #pragma unroll
    for (int i = 0; i < 8; i++)
        #pragma unroll
        for (int j = 0; j < 4; j++) acc2[i][j] = 0ULL;

    // prefetch offsets/mask for step 0
    float dy, dx, m;
    {
        int oidx = ((b * (2 * NS)) * HO + ho) * WO + wo;
        dy = __ldg(offset + oidx);
        dx = __ldg(offset + oidx + HO * WO);
        m  = __ldg(mask + (b * NS * HO + ho) * WO + wo);
    }

    for (int s = 0; s < NS; s++) {
        __syncthreads();   // previous GEMM done reading tiles

        // ---- stage pre-duplicated weight slice ----
        {
            const float4* wsrc = (const float4*)(g_wt + s * (CG * COUT));
            #pragma unroll
            for (int i = 0; i < 2; i++) {
                float4 v = wsrc[t + 256 * i];
                int base = 4 * (t + 256 * i);
                int c  = base >> 7;
                int co = base & 127;
                ulonglong2 d0, d1;
                d0.x = pack2(v.x, v.x);  d0.y = pack2(v.y, v.y);
                d1.x = pack2(v.z, v.z);  d1.y = pack2(v.w, v.w);
                *(ulonglong2*)&w_dup[c][co]     = d0;
                *(ulonglong2*)&w_dup[c][co + 2] = d1;
            }
        }

        // ---- sampling: 8 channels for pixel wo at position s ----
        {
            int dg = s / KK;
            int k  = s - dg * KK;
            int ky = k / 3, kx = k - ky * 3;

            float sy = dy + (float)(ho - 1 + ky);   // STRIDE=1, PAD=1, DIL=1
            float sx = dx + (float)(wo - 1 + kx);
            float y0f = floorf(sy), x0f = floorf(sx);
            float ly = sy - y0f, lx = sx - x0f;
            int y0 = (int)y0f, x0 = (int)x0f;

            float w00 = (1.0f - ly) * (1.0f - lx) * m;
            float w01 = (1.0f - ly) * lx * m;
            float w10 = ly * (1.0f - lx) * m;
            float w11 = ly * lx * m;

            const float* xbase = g_xt + (b * DGN + dg) * (HN * WN * CG) + ch;

            float val[8];
            #pragma unroll
            for (int c = 0; c < 8; c++) val[c] = 0.0f;

            int   ys[4] = {y0, y0, y0 + 1, y0 + 1};
            int   xs[4] = {x0, x0 + 1, x0, x0 + 1};
            float wb[4] = {w00, w01, w10, w11};
            #pragma unroll
            for (int cn = 0; cn < 4; cn++) {
                int yy = ys[cn], xx = xs[cn];
                if (yy >= 0 && yy < HN && xx >= 0 && xx < WN) {
                    const float4* p = (const float4*)(xbase + (yy * WN + xx) * CG);
                    float wg = wb[cn];
                    float4 v0 = p[0];
                    float4 v1 = p[1];
                    val[0] += wg * v0.x;  val[1] += wg * v0.y;
                    val[2] += wg * v0.z;  val[3] += wg * v0.w;
                    val[4] += wg * v1.x;  val[5] += wg * v1.y;
                    val[6] += wg * v1.z;  val[7] += wg * v1.w;
                }
            }
            #pragma unroll
            for (int c = 0; c < 8; c++) s_tile[ch + c][wo] = val[c];

            // prefetch offsets/mask for next step (hidden under GEMM)
            if (s + 1 < NS) {
                int oidx = ((b * (2 * NS) + 2 * (s + 1)) * HO + ho) * WO + wo;
                dy = __ldg(offset + oidx);
                dx = __ldg(offset + oidx + HO * WO);
                m  = __ldg(mask + ((b * NS + s + 1) * HO + ho) * WO + wo);
            }
        }
        __syncthreads();

        // ---- GEMM micro-step: 16 channels, pure FFMA2 ----
        #pragma unroll
        for (int c = 0; c < 16; c++) {
            ulonglong2 sA = *(const ulonglong2*)&s_tile[c][p_base];
            ulonglong2 sB = *(const ulonglong2*)&s_tile[c][p_base + 4];
            u64 sp0 = sA.x, sp1 = sA.y, sp2 = sB.x, sp3 = sB.y;
            const ulonglong2* wp = (const ulonglong2*)&w_dup[c][co_base];
            #pragma unroll
            for (int i = 0; i < 4; i++) {
                ulonglong2 w2 = wp[i];
                ffma2(acc2[2 * i][0], w2.x, sp0);
                ffma2(acc2[2 * i][1], w2.x, sp1);
                ffma2(acc2[2 * i][2], w2.x, sp2);
                ffma2(acc2[2 * i][3], w2.x, sp3);
                ffma2(acc2[2 * i + 1][0], w2.y, sp0);
                ffma2(acc2[2 * i + 1][1], w2.y, sp1);
                ffma2(acc2[2 * i + 1][2], w2.y, sp2);
                ffma2(acc2[2 * i + 1][3], w2.y, sp3);
            }
        }
    }

    // ---- epilogue ----
    union { u64 u; float2 f; } cv;
    #pragma unroll
    for (int i = 0; i < 8; i++) {
        int co = co_base + i;
        float bv = __ldg(bias + co);
        float r[8];
        #pragma unroll
        for (int j = 0; j < 4; j++) {
            cv.u = acc2[i][j];
            r[2 * j]     = cv.f.x + bv;
            r[2 * j + 1] = cv.f.y + bv;
        }
        float* op = out + ((b * COUT + co) * HO + ho) * WO + p_base;
        *(float4*)op       = make_float4(r[0], r[1], r[2], r[3]);
        *(float4*)(op + 4) = make_float4(r[4], r[5], r[6], r[7]);
    }
}

// ---------------------------------------------------------------------------
// Launch
// ---------------------------------------------------------------------------
extern "C" void kernel_launch(void* const* d_in, const int* in_sizes, int n_in,
                              void* d_out, int out_size) {
    const float* x      = (const float*)d_in[0];
    const float* offset = (const float*)d_in[1];
    const float* mask   = (const float*)d_in[2];
    const float* weight = (const float*)d_in[3];
    const float* bias   = (const float*)d_in[4];
    float* out = (float*)d_out;

    transpose_x_kernel<<<BN * DGN * HN, 128>>>(x);
    transpose_w_kernel<<<(NS * CG * COUT + 255) / 256, 256>>>(weight);
    dcn_main_kernel<<<BN * HO, 256>>>(offset, mask, bias, out);
}

// round 5
// speedup vs baseline: 1.9241x; 1.9241x over previous
#include <cuda_runtime.h>
#include <cstdint>

// Problem constants
#define BN   4
#define CN   128
#define HN   128
#define WN   128
#define COUT 128
#define DGN  8
#define CG   16
#define KK   9
#define HO   128
#define WO   128
#define NS   72         // (dg,k) positions
#define KT   (NS * 2)   // k8 slices (K = 1152 = 144 * 8)

// Scratch
__device__ __align__(16) float g_xt[BN * DGN * HN * WN * CG];    // x -> (B,DG,H,W,Cg)
__device__ __align__(16) uint32_t g_wa[KT * 8 * 32 * 4];         // A-fragment-ordered tf32 weights

__device__ __forceinline__ uint32_t f2tf32(float v) {
    uint32_t r;
    asm("cvt.rna.tf32.f32 %0, %1;" : "=r"(r) : "f"(v));
    return r;
}

__device__ __forceinline__ void mma_tf32(float* d, const uint32_t* a, const uint32_t* b) {
    asm volatile(
        "mma.sync.aligned.m16n8k8.row.col.f32.tf32.tf32.f32 "
        "{%0,%1,%2,%3}, {%4,%5,%6,%7}, {%8,%9}, {%0,%1,%2,%3};"
        : "+f"(d[0]), "+f"(d[1]), "+f"(d[2]), "+f"(d[3])
        : "r"(a[0]), "r"(a[1]), "r"(a[2]), "r"(a[3]), "r"(b[0]), "r"(b[1]));
}

// ---------------------------------------------------------------------------
// Kernel 1: transpose x (B,C,H,W) -> (B, DG, H, W, Cg)
// ---------------------------------------------------------------------------
__global__ void transpose_x_kernel(const float* __restrict__ x) {
    int blk = blockIdx.x;
    int y   = blk & (HN - 1);
    int bdg = blk >> 7;
    int b   = bdg >> 3;
    int dg  = bdg & 7;
    int t   = threadIdx.x;

    __shared__ float sm[CG][WN + 1];
    #pragma unroll
    for (int c = 0; c < CG; c++)
        sm[c][t] = x[((b * CN + dg * CG + c) * HN + y) * WN + t];
    __syncthreads();

    float* outp = g_xt + ((bdg * HN + y) * WN + t) * CG;
    #pragma unroll
    for (int i = 0; i < 4; i++) {
        float4 v = make_float4(sm[i * 4 + 0][t], sm[i * 4 + 1][t],
                               sm[i * 4 + 2][t], sm[i * 4 + 3][t]);
        *(float4*)(outp + i * 4) = v;
    }
}

// ---------------------------------------------------------------------------
// Kernel 2: weight (Cout,C,3,3) -> A-fragment-ordered tf32.
// For k8-slice kt (stage s = kt>>1, channel base (kt&1)*8), m16-tile mt,
// lane l (g = l>>2, tid = l&3), frag regs j:
//   j=0: (co=mt*16+g,   col=tid)    j=1: (co=mt*16+g+8, col=tid)
//   j=2: (co=mt*16+g,   col=tid+4)  j=3: (co=mt*16+g+8, col=tid+4)
// ---------------------------------------------------------------------------
__global__ void prep_w_kernel(const float* __restrict__ w) {
    int i = blockIdx.x * 256 + threadIdx.x;
    if (i >= KT * 8 * 32 * 4) return;
    int j    = i & 3;
    int lane = (i >> 2) & 31;
    int mt   = (i >> 7) & 7;
    int kt   = i >> 10;
    int g    = lane >> 2;
    int tid  = lane & 3;
    int co   = mt * 16 + g + ((j & 1) ? 8 : 0);
    int col  = tid + ((j >= 2) ? 4 : 0);
    int s    = kt >> 1;
    int c    = (kt & 1) * 8 + col;     // channel within group (0..15)
    int dg   = s / KK;
    int k    = s - dg * KK;
    float v = w[(co * CN + dg * CG + c) * KK + k];
    g_wa[i] = f2tf32(v);
}

// ---------------------------------------------------------------------------
// Kernel 3: fused deformable sampling + tf32 mma.sync implicit GEMM.
// One block per (b,ho): 128 px x 128 Cout, 256 threads / 8 warps.
// Warp wid: co 64*(wid>>2), px 32*(wid&3); tile 64x32 = 4x4 m16n8k8 per k8.
// Samplers write B fragments directly; A staged as flat copy of g_wa slice.
// ---------------------------------------------------------------------------
__global__ __launch_bounds__(256)
void dcn_main_kernel(const float* __restrict__ offset,
                     const float* __restrict__ mask,
                     const float* __restrict__ bias,
                     float*       __restrict__ out) {
    int blk = blockIdx.x;
    int ho  = blk & (HO - 1);
    int b   = blk >> 7;
    int t   = threadIdx.x;
    int wid = t >> 5;
    int lane = t & 31;

    // B fragments: [ktile(2)][ntile(16)][lane(32)] x uint2  = 8KB
    __shared__ __align__(16) uint2 bfrag[2][16][32];
    // A fragments: [ktile(2)][mtile(8)][lane(32)] x uint4    = 8KB
    __shared__ __align__(16) uint4 afrag[2][8][32];

    int m0 = (wid >> 2) * 4;   // first mtile of this warp
    int n0 = (wid & 3) * 4;    // first ntile of this warp

    // sampling role
    int wo    = t & (WO - 1);
    int ktile = t >> 7;          // 0 or 1
    int ch    = ktile * 8;

    float d[4][4][4];
    #pragma unroll
    for (int mi = 0; mi < 4; mi++)
        #pragma unroll
        for (int ni = 0; ni < 4; ni++)
            #pragma unroll
            for (int j = 0; j < 4; j++) d[mi][ni][j] = 0.0f;

    // prefetch offsets/mask for stage 0
    float dy, dx, m;
    {
        int oidx = ((b * (2 * NS)) * HO + ho) * WO + wo;
        dy = __ldg(offset + oidx);
        dx = __ldg(offset + oidx + HO * WO);
        m  = __ldg(mask + (b * NS * HO + ho) * WO + wo);
    }

    for (int s = 0; s < NS; s++) {
        __syncthreads();   // previous GEMM done reading fragments

        // ---- stage A fragments: flat 8KB copy (2 float4 per thread) ----
        {
            const uint4* wsrc = (const uint4*)(g_wa + s * 2048);
            uint4* wdst = (uint4*)&afrag[0][0][0];
            wdst[t]       = wsrc[t];
            wdst[t + 256] = wsrc[t + 256];
        }

        // ---- sampling: 8 channels for pixel wo at position s ----
        {
            int dg = s / KK;
            int k  = s - dg * KK;
            int ky = k / 3, kx = k - ky * 3;

            float sy = dy + (float)(ho - 1 + ky);   // STRIDE=1, PAD=1, DIL=1
            float sx = dx + (float)(wo - 1 + kx);
            float y0f = floorf(sy), x0f = floorf(sx);
            float ly = sy - y0f, lx = sx - x0f;
            int y0 = (int)y0f, x0 = (int)x0f;

            float w00 = (1.0f - ly) * (1.0f - lx) * m;
            float w01 = (1.0f - ly) * lx * m;
            float w10 = ly * (1.0f - lx) * m;
            float w11 = ly * lx * m;

            const float* xbase = g_xt + (b * DGN + dg) * (HN * WN * CG) + ch;

            float val[8];
            #pragma unroll
            for (int c = 0; c < 8; c++) val[c] = 0.0f;

            int   ys[4] = {y0, y0, y0 + 1, y0 + 1};
            int   xs[4] = {x0, x0 + 1, x0, x0 + 1};
            float wb[4] = {w00, w01, w10, w11};
            #pragma unroll
            for (int cn = 0; cn < 4; cn++) {
                int yy = ys[cn], xx = xs[cn];
                if (yy >= 0 && yy < HN && xx >= 0 && xx < WN) {
                    const float4* p = (const float4*)(xbase + (yy * WN + xx) * CG);
                    float wg = wb[cn];
                    float4 v0 = p[0];
                    float4 v1 = p[1];
                    val[0] += wg * v0.x;  val[1] += wg * v0.y;
                    val[2] += wg * v0.z;  val[3] += wg * v0.w;
                    val[4] += wg * v1.x;  val[5] += wg * v1.y;
                    val[6] += wg * v1.z;  val[7] += wg * v1.w;
                }
            }

            // write B fragments: lane = (wo%8)*4 + r, col=wo%8, rows r / r+4
            #pragma unroll
            for (int r = 0; r < 4; r++) {
                uint2 u = make_uint2(f2tf32(val[r]), f2tf32(val[r + 4]));
                bfrag[ktile][wo >> 3][(wo & 7) * 4 + r] = u;
            }

            // prefetch offsets/mask for next stage
            if (s + 1 < NS) {
                int oidx = ((b * (2 * NS) + 2 * (s + 1)) * HO + ho) * WO + wo;
                dy = __ldg(offset + oidx);
                dx = __ldg(offset + oidx + HO * WO);
                m  = __ldg(mask + ((b * NS + s + 1) * HO + ho) * WO + wo);
            }
        }
        __syncthreads();

        // ---- GEMM: 2 k8-slices x 4 mtiles x 4 ntiles m16n8k8 ----
        #pragma unroll
        for (int kt2 = 0; kt2 < 2; kt2++) {
            uint4 af[4];
            #pragma unroll
            for (int mi = 0; mi < 4; mi++) af[mi] = afrag[kt2][m0 + mi][lane];
            uint2 bf[4];
            #pragma unroll
            for (int ni = 0; ni < 4; ni++) bf[ni] = bfrag[kt2][n0 + ni][lane];
            #pragma unroll
            for (int mi = 0; mi < 4; mi++)
                #pragma unroll
                for (int ni = 0; ni < 4; ni++)
                    mma_tf32(d[mi][ni], (const uint32_t*)&af[mi],
                             (const uint32_t*)&bf[ni]);
        }
    }

    // ---- epilogue: c0:(g,2tid) c1:(g,2tid+1) c2:(g+8,2tid) c3:(g+8,2tid+1)
    int g   = lane >> 2;
    int tid = lane & 3;
    #pragma unroll
    for (int mi = 0; mi < 4; mi++) {
        int co0 = (m0 + mi) * 16 + g;
        float bv0 = __ldg(bias + co0);
        float bv1 = __ldg(bias + co0 + 8);
        #pragma unroll
        for (int ni = 0; ni < 4; ni++) {
            int px = (n0 + ni) * 8 + 2 * tid;
            float2 o0 = make_float2(d[mi][ni][0] + bv0, d[mi][ni][1] + bv0);
            float2 o1 = make_float2(d[mi][ni][2] + bv1, d[mi][ni][3] + bv1);
            *(float2*)(out + ((b * COUT + co0)     * HO + ho) * WO + px) = o0;
            *(float2*)(out + ((b * COUT + co0 + 8) * HO + ho) * WO + px) = o1;
        }
    }
}

// ---------------------------------------------------------------------------
// Launch
// ---------------------------------------------------------------------------
extern "C" void kernel_launch(void* const* d_in, const int* in_sizes, int n_in,
                              void* d_out, int out_size) {
    const float* x      = (const float*)d_in[0];
    const float* offset = (const float*)d_in[1];
    const float* mask   = (const float*)d_in[2];
    const float* weight = (const float*)d_in[3];
    const float* bias   = (const float*)d_in[4];
    float* out = (float*)d_out;

    transpose_x_kernel<<<BN * DGN * HN, 128>>>(x);
    prep_w_kernel<<<(KT * 8 * 32 * 4 + 255) / 256, 256>>>(weight);
    dcn_main_kernel<<<BN * HO, 256>>>(offset, mask, bias, out);
}